// round 17
// baseline (speedup 1.0000x reference)
#include <cuda_runtime.h>
#include <cuda_fp16.h>
#include <cstdint>

#define N_NODES   20000
#define N_EDGES   320000
#define NUM_HEADS 8
#define NEG_SLOPE 0.2f

// ---------------- device scratch ----------------
__device__ __half g_node_tbl[N_NODES * 640];  // fp16: [0:256) ni_h, [256:512) nj_h, [512:640) msg part
__device__ float g_node_sum[N_NODES * NUM_HEADS];
__device__ float g_agg[N_NODES * 128];        // UNNORMALIZED sum of ex*msg
// fragment-major B (fp16 1-term): (cf*8 + ks)*32 + lane -> {b0, b1}
__device__ uint2 g_WNf[80 * 8 * 32];
__device__ uint2 g_WEf[48 * 8 * 32];
__device__ uint2 g_WOf[16 * 8 * 32];
__device__ float g_bN[640];
__device__ float g_bE[384];

// ---------------- helpers ----------------
__device__ __forceinline__ uint32_t smem_u32(const void* p) {
    uint32_t a;
    asm("{ .reg .u64 t; cvta.to.shared.u64 t, %1; cvt.u32.u64 %0, t; }" : "=r"(a) : "l"(p));
    return a;
}

#define LDSM_X4(r0, r1, r2, r3, addr) \
    asm volatile("ldmatrix.sync.aligned.m8n8.x4.shared.b16 {%0,%1,%2,%3}, [%4];" \
                 : "=r"(r0), "=r"(r1), "=r"(r2), "=r"(r3) : "r"(addr))

#define MMA_F16(c, a, b0, b1) \
    asm volatile("mma.sync.aligned.m16n8k16.row.col.f32.f16.f16.f32 " \
                 "{%0,%1,%2,%3}, {%4,%5,%6,%7}, {%8,%9}, {%0,%1,%2,%3};" \
                 : "+f"((c)[0]), "+f"((c)[1]), "+f"((c)[2]), "+f"((c)[3]) \
                 : "r"((a)[0]), "r"((a)[1]), "r"((a)[2]), "r"((a)[3]), \
                   "r"(b0), "r"(b1))

__device__ __forceinline__ void quad_transpose(float2 e[4], int lid) {
    {
        bool hi = (lid & 2);
        float2 s0 = hi ? e[0] : e[2];
        float2 s1 = hi ? e[1] : e[3];
        s0.x = __shfl_xor_sync(0xffffffffu, s0.x, 2);
        s0.y = __shfl_xor_sync(0xffffffffu, s0.y, 2);
        s1.x = __shfl_xor_sync(0xffffffffu, s1.x, 2);
        s1.y = __shfl_xor_sync(0xffffffffu, s1.y, 2);
        if (hi) { e[0] = s0; e[1] = s1; } else { e[2] = s0; e[3] = s1; }
    }
    {
        bool od = (lid & 1);
        float2 s0 = od ? e[0] : e[1];
        float2 s1 = od ? e[2] : e[3];
        s0.x = __shfl_xor_sync(0xffffffffu, s0.x, 1);
        s0.y = __shfl_xor_sync(0xffffffffu, s0.y, 1);
        s1.x = __shfl_xor_sync(0xffffffffu, s1.x, 1);
        s1.y = __shfl_xor_sync(0xffffffffu, s1.y, 1);
        if (od) { e[0] = s0; e[2] = s1; } else { e[1] = s0; e[3] = s1; }
    }
}

// load 8 fp16 -> two float4
__device__ __forceinline__ void ld_h8(const __half* p, float4& a, float4& b) {
    uint4 v = *(const uint4*)p;
    float2 f0 = __half22float2(*(__half2*)&v.x);
    float2 f1 = __half22float2(*(__half2*)&v.y);
    float2 f2 = __half22float2(*(__half2*)&v.z);
    float2 f3 = __half22float2(*(__half2*)&v.w);
    a = make_float4(f0.x, f0.y, f1.x, f1.y);
    b = make_float4(f2.x, f2.y, f3.x, f3.y);
}

#define APITCH_B 272
#define SM_AH 0
#define SM_AL 34816
#define SM_EX 34816
#define SMEM_NODE 34816
#define SMEM_EDGE 38912
#define SMEM_OUT  69632

// ---------------- fused init: zero + biases + fragment-major weight tables ----------------
__global__ void init_kernel(const float* __restrict__ Wni, const float* __restrict__ Wnj,
                            const float* __restrict__ We,  const float* __restrict__ Wm,
                            const float* __restrict__ Wo,
                            const float* __restrict__ bni, const float* __restrict__ bnj,
                            const float* __restrict__ be,  const float* __restrict__ bm) {
    int i = blockIdx.x * blockDim.x + threadIdx.x;
    const int NS = N_NODES * NUM_HEADS;
    const int TOT = NS + N_NODES * 128;
    if (i < NS) g_node_sum[i] = 0.f;
    else if (i < TOT) g_agg[i - NS] = 0.f;

    if (i < 640) g_bN[i] = (i < 256) ? bni[i] : (i < 512 ? bnj[i - 256] : 0.f);
    if (i < 384) g_bE[i] = (i < 256) ? be[i] : bm[i - 256];

    int lane = i & 31;
    int ks   = (i >> 5) & 7;
    int cf   = i >> 8;
    int n  = (cf << 3) + (lane >> 2);
    int k0 = (ks << 4) + ((lane & 3) << 1);

    if (i < 80 * 8 * 32) {     // WN: 640 logical rows
        const float* row;
        if (n < 256)      row = Wni + (size_t)n * 128;
        else if (n < 512) row = Wnj + (size_t)(n - 256) * 128;
        else              row = Wm + (size_t)(n - 512) * 256;
        __half2 b0 = __floats2half2_rn(row[k0],     row[k0 + 1]);
        __half2 b1 = __floats2half2_rn(row[k0 + 8], row[k0 + 9]);
        g_WNf[i] = make_uint2(*(uint32_t*)&b0, *(uint32_t*)&b1);
    }
    if (i < 48 * 8 * 32) {     // WE: 384 logical rows
        const float* row = (n < 256) ? (We + (size_t)n * 128)
                                     : (Wm + (size_t)(n - 256) * 256 + 128);
        __half2 b0 = __floats2half2_rn(row[k0],     row[k0 + 1]);
        __half2 b1 = __floats2half2_rn(row[k0 + 8], row[k0 + 9]);
        g_WEf[i] = make_uint2(*(uint32_t*)&b0, *(uint32_t*)&b1);
    }
    if (i < 16 * 8 * 32) {     // WO: 128 logical rows
        const float* row = Wo + (size_t)n * 128;
        __half2 b0 = __floats2half2_rn(row[k0],     row[k0 + 1]);
        __half2 b1 = __floats2half2_rn(row[k0 + 8], row[k0 + 9]);
        g_WOf[i] = make_uint2(*(uint32_t*)&b0, *(uint32_t*)&b1);
    }
}

// ---------------- node kernel: 256 threads, 1-term fp16, warp 32x32, fp16 table out ----
__global__ void __launch_bounds__(256, 3) node_kernel(
    const float* __restrict__ A, int M, int NB) {
    extern __shared__ char smem[];
    uint32_t sb = smem_u32(smem);
    int tid = threadIdx.x;
    int wid = tid >> 5, lid = tid & 31;
    int m0 = blockIdx.x * 128;
    int nt0 = blockIdx.y * NB;

#pragma unroll
    for (int u = tid; u < 4096; u += 256) {
        int r = u >> 5, c = (u & 31) << 2;
        int row = m0 + r;
        float4 v = make_float4(0.f, 0.f, 0.f, 0.f);
        if (row < M) v = *(const float4*)(A + (size_t)row * 128 + c);
        __half2 h01 = __floats2half2_rn(v.x, v.y);
        __half2 h23 = __floats2half2_rn(v.z, v.w);
        uint32_t off = r * APITCH_B + c * 2;
        *(uint2*)(smem + SM_AH + off) = make_uint2(*(uint32_t*)&h01, *(uint32_t*)&h23);
    }
    __syncthreads();

    int wm = wid >> 1, wn = wid & 1;
    int lr = lid & 15, lc = lid >> 4;
    int q  = lid >> 2, lq = lid & 3;

    int lrow[4];
    lrow[0] = wm * 32 + q;  lrow[1] = lrow[0] + 8;
    lrow[2] = lrow[0] + 16; lrow[3] = lrow[0] + 24;

    for (int ntl = 0; ntl < NB; ntl++) {
        int nt = nt0 + ntl;
        float acc[2][4][4];
#pragma unroll
        for (int mf = 0; mf < 2; mf++)
#pragma unroll
            for (int f = 0; f < 4; f++)
#pragma unroll
                for (int j = 0; j < 4; j++) acc[mf][f][j] = 0.f;

        const uint2* bp = g_WNf + (size_t)(nt * 8 + wn * 4) * 256 + lid;
#pragma unroll
        for (int ks = 0; ks < 8; ks++) {
            uint32_t a0[4], a1[4];
            uint32_t aoff = (uint32_t)((wm * 32 + lr) * APITCH_B + (ks * 16 + lc * 8) * 2);
            LDSM_X4(a0[0], a0[1], a0[2], a0[3], sb + SM_AH + aoff);
            LDSM_X4(a1[0], a1[1], a1[2], a1[3], sb + SM_AH + aoff + 16 * APITCH_B);
            uint2 bv0 = bp[0 * 256 + ks * 32];
            uint2 bv1 = bp[1 * 256 + ks * 32];
            uint2 bv2 = bp[2 * 256 + ks * 32];
            uint2 bv3 = bp[3 * 256 + ks * 32];
            MMA_F16(acc[0][0], a0, bv0.x, bv0.y);
            MMA_F16(acc[0][1], a0, bv1.x, bv1.y);
            MMA_F16(acc[0][2], a0, bv2.x, bv2.y);
            MMA_F16(acc[0][3], a0, bv3.x, bv3.y);
            MMA_F16(acc[1][0], a1, bv0.x, bv0.y);
            MMA_F16(acc[1][1], a1, bv1.x, bv1.y);
            MMA_F16(acc[1][2], a1, bv2.x, bv2.y);
            MMA_F16(acc[1][3], a1, bv3.x, bv3.y);
        }

        int cg = nt * 64 + wn * 32 + lq * 8;
        float4 b0 = *(const float4*)(g_bN + cg);
        float4 b1 = *(const float4*)(g_bN + cg + 4);
#pragma unroll
        for (int mf = 0; mf < 2; mf++) {
#pragma unroll
            for (int hh = 0; hh < 2; hh++) {
                int ri = 2 * mf + hh;
                float2 e[4];
                e[0] = make_float2(acc[mf][0][2 * hh], acc[mf][0][2 * hh + 1]);
                e[1] = make_float2(acc[mf][1][2 * hh], acc[mf][1][2 * hh + 1]);
                e[2] = make_float2(acc[mf][2][2 * hh], acc[mf][2][2 * hh + 1]);
                e[3] = make_float2(acc[mf][3][2 * hh], acc[mf][3][2 * hh + 1]);
                quad_transpose(e, lid);
                int row = m0 + lrow[ri];
                if (row < M) {
                    __half2 p0 = __floats2half2_rn(e[0].x + b0.x, e[0].y + b0.y);
                    __half2 p1 = __floats2half2_rn(e[1].x + b0.z, e[1].y + b0.w);
                    __half2 p2 = __floats2half2_rn(e[2].x + b1.x, e[2].y + b1.y);
                    __half2 p3 = __floats2half2_rn(e[3].x + b1.z, e[3].y + b1.w);
                    *(uint4*)(g_node_tbl + (size_t)row * 640 + cg) =
                        make_uint4(*(uint32_t*)&p0, *(uint32_t*)&p1,
                                   *(uint32_t*)&p2, *(uint32_t*)&p3);
                }
            }
        }
    }
}

// ---------------- edge kernel: 256 threads, 4 CTAs/SM, 1-term fp16, warp 32x32 ----------
__global__ void __launch_bounds__(256, 4) edge_kernel(
    const float* __restrict__ A, const int* __restrict__ EI, const float* __restrict__ AP) {
    extern __shared__ char smem[];
    uint32_t sb = smem_u32(smem);
    float* sEX = (float*)(smem + SM_EX);
    int tid = threadIdx.x;
    int wid = tid >> 5, lid = tid & 31;
    int m0 = blockIdx.x * 128;

#pragma unroll
    for (int u = tid; u < 4096; u += 256) {
        int r = u >> 5, c = (u & 31) << 2;
        float4 v = *(const float4*)(A + (size_t)(m0 + r) * 128 + c);
        __half2 h01 = __floats2half2_rn(v.x, v.y);
        __half2 h23 = __floats2half2_rn(v.z, v.w);
        uint32_t off = r * APITCH_B + c * 2;
        *(uint2*)(smem + SM_AH + off) = make_uint2(*(uint32_t*)&h01, *(uint32_t*)&h23);
    }
    __syncthreads();

    int wm = wid >> 1, wn = wid & 1;
    int lr = lid & 15, lc = lid >> 4;
    int q  = lid >> 2, lq = lid & 3;

    int lrow[4];
    lrow[0] = wm * 32 + q;  lrow[1] = lrow[0] + 8;
    lrow[2] = lrow[0] + 16; lrow[3] = lrow[0] + 24;
    int ss[4], dd[4];
#pragma unroll
    for (int i = 0; i < 4; i++) {
        int e = m0 + lrow[i];
        ss[i] = EI[e]; dd[i] = EI[N_EDGES + e];
    }

    for (int nt = 0; nt < 6; nt++) {
        float acc[2][4][4];
#pragma unroll
        for (int mf = 0; mf < 2; mf++)
#pragma unroll
            for (int f = 0; f < 4; f++)
#pragma unroll
                for (int j = 0; j < 4; j++) acc[mf][f][j] = 0.f;

        const uint2* bp = g_WEf + (size_t)(nt * 8 + wn * 4) * 256 + lid;
#pragma unroll
        for (int ks = 0; ks < 8; ks++) {
            uint32_t a0[4], a1[4];
            uint32_t aoff = (uint32_t)((wm * 32 + lr) * APITCH_B + (ks * 16 + lc * 8) * 2);
            LDSM_X4(a0[0], a0[1], a0[2], a0[3], sb + SM_AH + aoff);
            LDSM_X4(a1[0], a1[1], a1[2], a1[3], sb + SM_AH + aoff + 16 * APITCH_B);
            uint2 bv0 = bp[0 * 256 + ks * 32];
            uint2 bv1 = bp[1 * 256 + ks * 32];
            uint2 bv2 = bp[2 * 256 + ks * 32];
            uint2 bv3 = bp[3 * 256 + ks * 32];
            MMA_F16(acc[0][0], a0, bv0.x, bv0.y);
            MMA_F16(acc[0][1], a0, bv1.x, bv1.y);
            MMA_F16(acc[0][2], a0, bv2.x, bv2.y);
            MMA_F16(acc[0][3], a0, bv3.x, bv3.y);
            MMA_F16(acc[1][0], a1, bv0.x, bv0.y);
            MMA_F16(acc[1][1], a1, bv1.x, bv1.y);
            MMA_F16(acc[1][2], a1, bv2.x, bv2.y);
            MMA_F16(acc[1][3], a1, bv3.x, bv3.y);
        }

        int cg = nt * 64 + wn * 32 + lq * 8;
        if (nt < 4) {
            int head = nt * 2 + wn;
            float4 b0  = *(const float4*)(g_bE + cg);
            float4 b1  = *(const float4*)(g_bE + cg + 4);
            float4 ap0 = *(const float4*)(AP + head * 32 + lq * 8);
            float4 ap1 = *(const float4*)(AP + head * 32 + lq * 8 + 4);
#pragma unroll
            for (int mf = 0; mf < 2; mf++) {
                float p0, p1;
                {
                    float2 e[4];
                    e[0] = make_float2(acc[mf][0][0], acc[mf][0][1]);
                    e[1] = make_float2(acc[mf][1][0], acc[mf][1][1]);
                    e[2] = make_float2(acc[mf][2][0], acc[mf][2][1]);
                    e[3] = make_float2(acc[mf][3][0], acc[mf][3][1]);
                    quad_transpose(e, lid);
                    float4 i0, i1, j0, j1;
                    ld_h8(g_node_tbl + (size_t)ss[2 * mf] * 640 + cg, i0, i1);
                    ld_h8(g_node_tbl + (size_t)dd[2 * mf] * 640 + 256 + cg, j0, j1);
                    float h; p0 = 0.f;
                    h = e[0].x + b0.x + i0.x + j0.x; h = (h >= 0.f) ? h : NEG_SLOPE * h; p0 += h * ap0.x;
                    h = e[0].y + b0.y + i0.y + j0.y; h = (h >= 0.f) ? h : NEG_SLOPE * h; p0 += h * ap0.y;
                    h = e[1].x + b0.z + i0.z + j0.z; h = (h >= 0.f) ? h : NEG_SLOPE * h; p0 += h * ap0.z;
                    h = e[1].y + b0.w + i0.w + j0.w; h = (h >= 0.f) ? h : NEG_SLOPE * h; p0 += h * ap0.w;
                    h = e[2].x + b1.x + i1.x + j1.x; h = (h >= 0.f) ? h : NEG_SLOPE * h; p0 += h * ap1.x;
                    h = e[2].y + b1.y + i1.y + j1.y; h = (h >= 0.f) ? h : NEG_SLOPE * h; p0 += h * ap1.y;
                    h = e[3].x + b1.z + i1.z + j1.z; h = (h >= 0.f) ? h : NEG_SLOPE * h; p0 += h * ap1.z;
                    h = e[3].y + b1.w + i1.w + j1.w; h = (h >= 0.f) ? h : NEG_SLOPE * h; p0 += h * ap1.w;
                }
                {
                    float2 e[4];
                    e[0] = make_float2(acc[mf][0][2], acc[mf][0][3]);
                    e[1] = make_float2(acc[mf][1][2], acc[mf][1][3]);
                    e[2] = make_float2(acc[mf][2][2], acc[mf][2][3]);
                    e[3] = make_float2(acc[mf][3][2], acc[mf][3][3]);
                    quad_transpose(e, lid);
                    float4 i0, i1, j0, j1;
                    ld_h8(g_node_tbl + (size_t)ss[2 * mf + 1] * 640 + cg, i0, i1);
                    ld_h8(g_node_tbl + (size_t)dd[2 * mf + 1] * 640 + 256 + cg, j0, j1);
                    float h; p1 = 0.f;
                    h = e[0].x + b0.x + i0.x + j0.x; h = (h >= 0.f) ? h : NEG_SLOPE * h; p1 += h * ap0.x;
                    h = e[0].y + b0.y + i0.y + j0.y; h = (h >= 0.f) ? h : NEG_SLOPE * h; p1 += h * ap0.y;
                    h = e[1].x + b0.z + i0.z + j0.z; h = (h >= 0.f) ? h : NEG_SLOPE * h; p1 += h * ap0.z;
                    h = e[1].y + b0.w + i0.w + j0.w; h = (h >= 0.f) ? h : NEG_SLOPE * h; p1 += h * ap0.w;
                    h = e[2].x + b1.x + i1.x + j1.x; h = (h >= 0.f) ? h : NEG_SLOPE * h; p1 += h * ap1.x;
                    h = e[2].y + b1.y + i1.y + j1.y; h = (h >= 0.f) ? h : NEG_SLOPE * h; p1 += h * ap1.y;
                    h = e[3].x + b1.z + i1.z + j1.z; h = (h >= 0.f) ? h : NEG_SLOPE * h; p1 += h * ap1.z;
                    h = e[3].y + b1.w + i1.w + j1.w; h = (h >= 0.f) ? h : NEG_SLOPE * h; p1 += h * ap1.w;
                }
                p0 += __shfl_xor_sync(0xffffffffu, p0, 1);
                p0 += __shfl_xor_sync(0xffffffffu, p0, 2);
                p1 += __shfl_xor_sync(0xffffffffu, p1, 1);
                p1 += __shfl_xor_sync(0xffffffffu, p1, 2);
                if (lq == 0) {
                    float e0 = expf(p0), e1 = expf(p1);
                    sEX[lrow[2 * mf] * 8 + head]     = e0;
                    sEX[lrow[2 * mf + 1] * 8 + head] = e1;
                    atomicAdd(&g_node_sum[ss[2 * mf] * 8 + head], e0);
                    atomicAdd(&g_node_sum[ss[2 * mf + 1] * 8 + head], e1);
                }
            }
            if (nt == 3) __syncthreads();   // publish sEX before message phase
        } else {
            int cm = (nt - 4) * 64 + wn * 32 + lq * 8;
            int head = cm >> 4;
            float4 b0 = *(const float4*)(g_bE + 256 + cm);
            float4 b1 = *(const float4*)(g_bE + 256 + cm + 4);
#pragma unroll
            for (int mf = 0; mf < 2; mf++) {
#pragma unroll
                for (int hh = 0; hh < 2; hh++) {
                    int ri = 2 * mf + hh;
                    float2 e[4];
                    e[0] = make_float2(acc[mf][0][2 * hh], acc[mf][0][2 * hh + 1]);
                    e[1] = make_float2(acc[mf][1][2 * hh], acc[mf][1][2 * hh + 1]);
                    e[2] = make_float2(acc[mf][2][2 * hh], acc[mf][2][2 * hh + 1]);
                    e[3] = make_float2(acc[mf][3][2 * hh], acc[mf][3][2 * hh + 1]);
                    quad_transpose(e, lid);
                    float ex = sEX[lrow[ri] * 8 + head];
                    float4 n0, n1;
                    ld_h8(g_node_tbl + (size_t)dd[ri] * 640 + 512 + cm, n0, n1);
                    float* dst = g_agg + (size_t)ss[ri] * 128 + cm;
                    asm volatile("red.global.add.v4.f32 [%0], {%1,%2,%3,%4};"
                                 :: "l"(dst),
                                    "f"((e[0].x + b0.x + n0.x) * ex), "f"((e[0].y + b0.y + n0.y) * ex),
                                    "f"((e[1].x + b0.z + n0.z) * ex), "f"((e[1].y + b0.w + n0.w) * ex) : "memory");
                    asm volatile("red.global.add.v4.f32 [%0], {%1,%2,%3,%4};"
                                 :: "l"(dst + 4),
                                    "f"((e[2].x + b1.x + n1.x) * ex), "f"((e[2].y + b1.y + n1.y) * ex),
                                    "f"((e[3].x + b1.z + n1.z) * ex), "f"((e[3].y + b1.w + n1.w) * ex) : "memory");
                }
            }
        }
    }
}

// ---------------- output kernel: normalized A (2-term hi/lo fp16) x WOf, fp32 out ---------
__global__ void __launch_bounds__(256, 3) out_kernel(
    const float* __restrict__ bo, float* __restrict__ C, int M) {
    extern __shared__ char smem[];
    uint32_t sb = smem_u32(smem);
    int tid = threadIdx.x;
    int wid = tid >> 5, lid = tid & 31;
    int m0 = blockIdx.x * 128;

    // A-fill: agg / sum -> hi/lo fp16
#pragma unroll
    for (int u = tid; u < 4096; u += 256) {
        int r = u >> 5, c = (u & 31) << 2;
        int row = m0 + r;
        float4 v = make_float4(0.f, 0.f, 0.f, 0.f);
        if (row < M) {
            v = *(const float4*)(g_agg + (size_t)row * 128 + c);
            float inv = 1.0f / g_node_sum[row * 8 + (c >> 4)];
            v.x *= inv; v.y *= inv; v.z *= inv; v.w *= inv;
        }
        __half2 h01 = __floats2half2_rn(v.x, v.y);
        __half2 h23 = __floats2half2_rn(v.z, v.w);
        float2 f01 = __half22float2(h01);
        float2 f23 = __half22float2(h23);
        __half2 l01 = __floats2half2_rn(v.x - f01.x, v.y - f01.y);
        __half2 l23 = __floats2half2_rn(v.z - f23.x, v.w - f23.y);
        uint32_t off = r * APITCH_B + c * 2;
        *(uint2*)(smem + SM_AH + off) = make_uint2(*(uint32_t*)&h01, *(uint32_t*)&h23);
        *(uint2*)(smem + SM_AL + off) = make_uint2(*(uint32_t*)&l01, *(uint32_t*)&l23);
    }
    __syncthreads();

    int wm = wid >> 1, wn = wid & 1;
    int lr = lid & 15, lc = lid >> 4;
    int q  = lid >> 2, lq = lid & 3;

    int lrow[4];
    lrow[0] = wm * 32 + q;  lrow[1] = lrow[0] + 8;
    lrow[2] = lrow[0] + 16; lrow[3] = lrow[0] + 24;

    for (int nt = 0; nt < 2; nt++) {
        float acc[2][4][4];
#pragma unroll
        for (int mf = 0; mf < 2; mf++)
#pragma unroll
            for (int f = 0; f < 4; f++)
#pragma unroll
                for (int j = 0; j < 4; j++) acc[mf][f][j] = 0.f;

        const uint2* bp = g_WOf + (size_t)(nt * 8 + wn * 4) * 256 + lid;
#pragma unroll
        for (int ks = 0; ks < 8; ks++) {
            uint32_t a0h[4], a1h[4], a0l[4], a1l[4];
            uint32_t aoff = (uint32_t)((wm * 32 + lr) * APITCH_B + (ks * 16 + lc * 8) * 2);
            LDSM_X4(a0h[0], a0h[1], a0h[2], a0h[3], sb + SM_AH + aoff);
            LDSM_X4(a1h[0], a1h[1], a1h[2], a1h[3], sb + SM_AH + aoff + 16 * APITCH_B);
            LDSM_X4(a0l[0], a0l[1], a0l[2], a0l[3], sb + SM_AL + aoff);
            LDSM_X4(a1l[0], a1l[1], a1l[2], a1l[3], sb + SM_AL + aoff + 16 * APITCH_B);
            uint2 bv0 = bp[0 * 256 + ks * 32];
            uint2 bv1 = bp[1 * 256 + ks * 32];
            uint2 bv2 = bp[2 * 256 + ks * 32];
            uint2 bv3 = bp[3 * 256 + ks * 32];
            MMA_F16(acc[0][0], a0h, bv0.x, bv0.y);
            MMA_F16(acc[0][0], a0l, bv0.x, bv0.y);
            MMA_F16(acc[0][1], a0h, bv1.x, bv1.y);
            MMA_F16(acc[0][1], a0l, bv1.x, bv1.y);
            MMA_F16(acc[0][2], a0h, bv2.x, bv2.y);
            MMA_F16(acc[0][2], a0l, bv2.x, bv2.y);
            MMA_F16(acc[0][3], a0h, bv3.x, bv3.y);
            MMA_F16(acc[0][3], a0l, bv3.x, bv3.y);
            MMA_F16(acc[1][0], a1h, bv0.x, bv0.y);
            MMA_F16(acc[1][0], a1l, bv0.x, bv0.y);
            MMA_F16(acc[1][1], a1h, bv1.x, bv1.y);
            MMA_F16(acc[1][1], a1l, bv1.x, bv1.y);
            MMA_F16(acc[1][2], a1h, bv2.x, bv2.y);
            MMA_F16(acc[1][2], a1l, bv2.x, bv2.y);
            MMA_F16(acc[1][3], a1h, bv3.x, bv3.y);
            MMA_F16(acc[1][3], a1l, bv3.x, bv3.y);
        }

        int cg = nt * 64 + wn * 32 + lq * 8;
        float4 b0 = *(const float4*)(bo + cg);
        float4 b1 = *(const float4*)(bo + cg + 4);
#pragma unroll
        for (int mf = 0; mf < 2; mf++) {
#pragma unroll
            for (int hh = 0; hh < 2; hh++) {
                int ri = 2 * mf + hh;
                float2 e[4];
                e[0] = make_float2(acc[mf][0][2 * hh], acc[mf][0][2 * hh + 1]);
                e[1] = make_float2(acc[mf][1][2 * hh], acc[mf][1][2 * hh + 1]);
                e[2] = make_float2(acc[mf][2][2 * hh], acc[mf][2][2 * hh + 1]);
                e[3] = make_float2(acc[mf][3][2 * hh], acc[mf][3][2 * hh + 1]);
                quad_transpose(e, lid);
                int row = m0 + lrow[ri];
                if (row < M) {
                    float* dst = C + (size_t)row * 128 + cg;
                    *(float4*)dst       = make_float4(e[0].x + b0.x, e[0].y + b0.y, e[1].x + b0.z, e[1].y + b0.w);
                    *(float4*)(dst + 4) = make_float4(e[2].x + b1.x, e[2].y + b1.y, e[3].x + b1.z, e[3].y + b1.w);
                }
            }
        }
    }
}

// ---------------- launch ----------------
extern "C" void kernel_launch(void* const* d_in, const int* in_sizes, int n_in,
                              void* d_out, int out_size) {
    const float* node_features = (const float*)d_in[0];
    const float* edge_features = (const float*)d_in[1];
    const int*   edge_index    = (const int*)d_in[2];
    const float* Wni = (const float*)d_in[3];
    const float* bni = (const float*)d_in[4];
    const float* Wnj = (const float*)d_in[5];
    const float* bnj = (const float*)d_in[6];
    const float* We  = (const float*)d_in[7];
    const float* be  = (const float*)d_in[8];
    const float* attn_proj = (const float*)d_in[9];
    const float* Wm  = (const float*)d_in[10];
    const float* bm  = (const float*)d_in[11];
    const float* Wo  = (const float*)d_in[12];
    const float* bo  = (const float*)d_in[13];
    float* out = (float*)d_out;

    static bool attr_set = false;
    if (!attr_set) {
        cudaFuncSetAttribute(node_kernel, cudaFuncAttributeMaxDynamicSharedMemorySize, SMEM_NODE);
        cudaFuncSetAttribute(edge_kernel, cudaFuncAttributeMaxDynamicSharedMemorySize, SMEM_EDGE);
        cudaFuncSetAttribute(out_kernel,  cudaFuncAttributeMaxDynamicSharedMemorySize, SMEM_OUT);
        attr_set = true;
    }

    const int ITOT = N_NODES * NUM_HEADS + N_NODES * 128;   // zero range dominates
    init_kernel<<<(ITOT + 255) / 256, 256>>>(Wni, Wnj, We, Wm, Wo, bni, bnj, be, bm);

    // node tables: 157 M-tiles x 2 halves, 5 N-tiles each
    node_kernel<<<dim3((N_NODES + 127) / 128, 2), 256, SMEM_NODE>>>(
        node_features, N_NODES, 5);

    // edge pass: 2500 M-tiles, 4 CTAs/SM
    edge_kernel<<<N_EDGES / 128, 256, SMEM_EDGE>>>(
        edge_features, edge_index, attn_proj);

    // output projection (tensorized, 2-term A split, normalization folded into A-fill)
    out_kernel<<<(N_NODES + 127) / 128, 256, SMEM_OUT>>>(bo, out, N_NODES);
}